// round 8
// baseline (speedup 1.0000x reference)
#include <cuda_runtime.h>

#define T_STEPS 8192
#define IDIM 256
#define HDIM 1024
#define NBLOCKS 128
#define NTHREADS 256       // 8 warps; warp w handles h index j = 8*block + w
#define NAN_BITS 0x7fc00000u

// h history: row t holds h_{t-1} (input to step t). Row 0 = zeros (h_0).
// Rows 1..T start as sentinel NaN. Each element is written EXACTLY ONCE,
// so any non-sentinel read is the final value — the validated load IS the
// synchronization. h = o*tanh(c) ∈ (-1,1) never equals the sentinel.
__device__ __align__(16) float g_hs[(T_STEPS + 1) * HDIM];

// Fill row 0 with zeros, rows 1..T with sentinel. One block per row.
__global__ void init_kernel() {
    unsigned int v = (blockIdx.x == 0) ? 0u : NAN_BITS;
    uint4 q = make_uint4(v, v, v, v);
    reinterpret_cast<uint4*>(g_hs + (size_t)blockIdx.x * HDIM)[threadIdx.x] = q;
}

__device__ __forceinline__ float sigmoid_fast(float x) {
    return 1.0f / (1.0f + __expf(-x));
}

// Packed dual-FMA: d.xy += a.xy * b.xy  (Blackwell f32x2, PTX-only)
__device__ __forceinline__ void fma2(unsigned long long& d,
                                     unsigned long long a,
                                     unsigned long long b) {
    asm("fma.rn.f32x2 %0, %1, %2, %0;" : "+l"(d) : "l"(a), "l"(b));
}
__device__ __forceinline__ unsigned long long ld64(const float* p) {
    return *reinterpret_cast<const unsigned long long*>(p);
}
__device__ __forceinline__ float pairsum(unsigned long long v) {
    float2 f = *reinterpret_cast<float2*>(&v);
    return f.x + f.y;
}

__global__ void __launch_bounds__(NTHREADS, 1)
lstm_kernel(const float* __restrict__ seq,
            const float* __restrict__ W_ih,
            const float* __restrict__ W_hh,
            const float* __restrict__ b_ih,
            const float* __restrict__ b_hh)
{
    __shared__ __align__(16) float h_s[2][HDIM];   // double buffer, parity t&1

    const int tid  = threadIdx.x;
    const int warp = tid >> 5;
    const int lane = tid & 31;
    const int j    = blockIdx.x * 8 + warp;     // h index this warp owns
    const int gate = lane & 3;                  // gate this lane carries post-merge

    const int r[4] = { j, j + HDIM, j + 2 * HDIM, j + 3 * HDIM };

    // ---- Recurrent weights, register-resident as f32x2 pairs. ----
    unsigned long long wh[4][16];
    #pragma unroll
    for (int g = 0; g < 4; g++)
        #pragma unroll
        for (int k = 0; k < 16; k++)
            wh[g][k] = ld64(W_hh + (size_t)r[g] * HDIM + 2 * lane + 64 * k);

    // ---- Input-projection weights. ----
    unsigned long long wx[4][4];
    #pragma unroll
    for (int g = 0; g < 4; g++)
        #pragma unroll
        for (int k = 0; k < 4; k++)
            wx[g][k] = ld64(W_ih + (size_t)r[g] * IDIM + 2 * lane + 64 * k);

    // Per-lane bias + nonlinearity constants for the lane's gate:
    //   sigmoid(x) = 1/(1+exp(-x))          -> pre=-1, postA=1, postB=0
    //   tanh(x)    = 2/(1+exp(-2x)) - 1     -> pre=-2, postA=2, postB=-1 (gate 2)
    const float bias_lane = b_ih[r[gate]] + b_hh[r[gate]];
    const float pre   = (gate == 2) ? -2.0f : -1.0f;
    const float postA = (gate == 2) ?  2.0f :  1.0f;
    const float postB = (gate == 2) ? -1.0f :  0.0f;

    // x_t pairs, prefetched one step ahead
    unsigned long long xr[4];
    #pragma unroll
    for (int k = 0; k < 4; k++)
        xr[k] = ld64(seq + 2 * lane + 64 * k);

    float c_state = 0.0f;   // uniform across lanes

    #pragma unroll 1
    for (int t = 0; t < T_STEPS; ++t) {
        const int buf = t & 1;

        // ---- Speculative FIRST poll load, before any compute, so its L2
        // round trip overlaps the x-projection. ----
        const float* p = g_hs + (size_t)t * HDIM + 128 * warp + 4 * lane;
        unsigned int v0, v1, v2, v3;
        asm volatile("ld.global.cg.v4.b32 {%0,%1,%2,%3}, [%4];"
                     : "=r"(v0), "=r"(v1), "=r"(v2), "=r"(v3) : "l"(p));

        // ---- x-projection: independent of h_t, hides the poll RTT. ----
        unsigned long long a0 = 0, a1 = 0, a2 = 0, a3 = 0;
        #pragma unroll
        for (int k = 0; k < 4; k++) {
            fma2(a0, wx[0][k], xr[k]);
            fma2(a1, wx[1][k], xr[k]);
            fma2(a2, wx[2][k], xr[k]);
            fma2(a3, wx[3][k], xr[k]);
        }

        // ---- Warp-granular sentinel poll (sticky lanes, vote exit). ----
        int ok = (v0 != NAN_BITS) & (v1 != NAN_BITS) &
                 (v2 != NAN_BITS) & (v3 != NAN_BITS);
        while (!__all_sync(0xffffffffu, ok)) {
            if (!ok) {
                asm volatile("ld.global.cg.v4.b32 {%0,%1,%2,%3}, [%4];"
                             : "=r"(v0), "=r"(v1), "=r"(v2), "=r"(v3) : "l"(p));
                ok = (v0 != NAN_BITS) & (v1 != NAN_BITS) &
                     (v2 != NAN_BITS) & (v3 != NAN_BITS);
            }
        }

        // Stage this warp's segment; SOLE barrier of the step (double buffer:
        // h_s[buf] is next written at t+2, after BAR(t+1), after all reads at t).
        reinterpret_cast<uint4*>(h_s[buf])[tid] = make_uint4(v0, v1, v2, v3);
        __syncthreads();

        // ---- Recurrent matvec: register weights vs SMEM h, packed f32x2. ----
        const float* hb = h_s[buf] + 2 * lane;
        #pragma unroll
        for (int k = 0; k < 16; k++) {
            unsigned long long hv = ld64(hb + 64 * k);
            fma2(a0, wh[0][k], hv);
            fma2(a1, wh[1][k], hv);
            fma2(a2, wh[2][k], hv);
            fma2(a3, wh[3][k], hv);
        }

        float s0 = pairsum(a0), s1 = pairsum(a1),
              s2 = pairsum(a2), s3 = pairsum(a3);

        // ---- Merge stage 1 (xor 1): fold gates {0,1} and {2,3}.
        // After: bit0=0 lanes carry gate0/gate2 partials, bit0=1 carry 1/3. ----
        {
            bool hi = (lane & 1);
            float keep01 = hi ? s1 : s0, send01 = hi ? s0 : s1;
            float keep23 = hi ? s3 : s2, send23 = hi ? s2 : s3;
            s0 = keep01 + __shfl_xor_sync(0xffffffffu, send01, 1);
            s2 = keep23 + __shfl_xor_sync(0xffffffffu, send23, 1);
        }
        // ---- Merge stage 2 (xor 2): fold {01} and {23}. After: lane&3 == g
        // lanes carry gate g partials (8 lanes each). ----
        float w;
        {
            bool hi = (lane & 2);
            float keep = hi ? s2 : s0, send = hi ? s0 : s2;
            w = keep + __shfl_xor_sync(0xffffffffu, send, 2);
        }
        // ---- Butterfly over the 8-lane groups. ----
        w += __shfl_xor_sync(0xffffffffu, w, 4);
        w += __shfl_xor_sync(0xffffffffu, w, 8);
        w += __shfl_xor_sync(0xffffffffu, w, 16);

        // ---- ONE nonlinearity for all gates (per-lane constants). ----
        float act = fmaf(postA,
                         1.0f / (1.0f + __expf(pre * (w + bias_lane))),
                         postB);
        float i_ = __shfl_sync(0xffffffffu, act, 0);
        float f_ = __shfl_sync(0xffffffffu, act, 1);
        float g_ = __shfl_sync(0xffffffffu, act, 2);
        float o_ = __shfl_sync(0xffffffffu, act, 3);

        c_state = f_ * c_state + i_ * g_;
        float tc = fmaf(2.0f, 1.0f / (1.0f + __expf(-2.0f * c_state)), -1.0f);
        float h_ = o_ * tc;
        if (lane == 0) {
            asm volatile("st.global.cg.f32 [%0], %1;"
                         :: "l"(g_hs + (size_t)(t + 1) * HDIM + j), "f"(h_));
        }

        // ---- Prefetch x_{t+1}; latency hides behind the next poll. ----
        if (t + 1 < T_STEPS) {
            const float* xrow = seq + (size_t)(t + 1) * IDIM + 2 * lane;
            #pragma unroll
            for (int k = 0; k < 4; k++)
                xr[k] = ld64(xrow + 64 * k);
        }
    }
}

// out[t] = sigmoid(h_{t+1} . W_out + b_out); one warp per timestep.
__global__ void __launch_bounds__(256)
out_kernel(const float* __restrict__ W_out,
           const float* __restrict__ b_out,
           float* __restrict__ out)
{
    const int warp = threadIdx.x >> 5;
    const int lane = threadIdx.x & 31;
    const int t = blockIdx.x * 8 + warp;
    if (t >= T_STEPS) return;

    const float* hrow = g_hs + (size_t)(t + 1) * HDIM;
    float acc = 0.0f;
    #pragma unroll
    for (int k = 0; k < 32; k++) {
        int c = lane + 32 * k;
        acc = fmaf(hrow[c], W_out[c], acc);
    }
    #pragma unroll
    for (int off = 16; off > 0; off >>= 1)
        acc += __shfl_xor_sync(0xffffffffu, acc, off);
    if (lane == 0)
        out[t] = sigmoid_fast(acc + b_out[0]);
}

extern "C" void kernel_launch(void* const* d_in, const int* in_sizes, int n_in,
                              void* d_out, int out_size)
{
    const float* seq   = (const float*)d_in[0];   // [8192, 256]
    const float* W_ih  = (const float*)d_in[1];   // [4096, 256]
    const float* W_hh  = (const float*)d_in[2];   // [4096, 1024]
    const float* b_ih  = (const float*)d_in[3];   // [4096]
    const float* b_hh  = (const float*)d_in[4];   // [4096]
    const float* W_out = (const float*)d_in[5];   // [1, 1024]
    const float* b_out = (const float*)d_in[6];   // [1]
    float* out = (float*)d_out;                   // [8192, 1]

    init_kernel<<<T_STEPS + 1, NTHREADS>>>();
    lstm_kernel<<<NBLOCKS, NTHREADS>>>(seq, W_ih, W_hh, b_ih, b_hh);
    out_kernel<<<T_STEPS / 8, 256>>>(W_out, b_out, out);
}

// round 9
// speedup vs baseline: 2.7967x; 2.7967x over previous
#include <cuda_runtime.h>

#define T_STEPS 8192
#define IDIM 256
#define HDIM 1024
#define NBLOCKS 128
#define NTHREADS 256       // 8 warps; warp w handles h index j = 8*block + w
#define NAN_BITS 0x7fc00000u

// h history: row t holds h_{t-1} (input to step t). Row 0 = zeros (h_0).
// Rows 1..T start as sentinel NaN. Each element is written EXACTLY ONCE,
// so any non-sentinel read is the final value — the validated load IS the
// synchronization. h = o*tanh(c) ∈ (-1,1) never equals the sentinel.
__device__ __align__(16) float g_hs[(T_STEPS + 1) * HDIM];

// Fill row 0 with zeros, rows 1..T with sentinel. One block per row.
__global__ void init_kernel() {
    unsigned int v = (blockIdx.x == 0) ? 0u : NAN_BITS;
    uint4 q = make_uint4(v, v, v, v);
    reinterpret_cast<uint4*>(g_hs + (size_t)blockIdx.x * HDIM)[threadIdx.x] = q;
}

__device__ __forceinline__ float sigmoid_fast(float x) {
    return 1.0f / (1.0f + __expf(-x));
}

// Packed dual-FMA: d.xy += a.xy * b.xy  (Blackwell f32x2, PTX-only)
__device__ __forceinline__ void fma2(unsigned long long& d,
                                     unsigned long long a,
                                     unsigned long long b) {
    asm("fma.rn.f32x2 %0, %1, %2, %0;" : "+l"(d) : "l"(a), "l"(b));
}
__device__ __forceinline__ unsigned long long ld64(const float* p) {
    return *reinterpret_cast<const unsigned long long*>(p);
}
__device__ __forceinline__ float pairsum(unsigned long long v) {
    float2 f = *reinterpret_cast<float2*>(&v);
    return f.x + f.y;
}

__global__ void __launch_bounds__(NTHREADS, 1)
lstm_kernel(const float* __restrict__ seq,
            const float* __restrict__ W_ih,
            const float* __restrict__ W_hh,
            const float* __restrict__ b_ih,
            const float* __restrict__ b_hh)
{
    __shared__ __align__(16) float h_s[HDIM];   // single buffer (R6 structure)

    const int tid  = threadIdx.x;
    const int warp = tid >> 5;
    const int lane = tid & 31;
    const int j    = blockIdx.x * 8 + warp;     // h index this warp owns
    const int gate = lane & 3;                  // gate this lane carries post-merge

    const int r0 = j;
    const int r1 = j + HDIM;
    const int r2 = j + 2 * HDIM;
    const int r3 = j + 3 * HDIM;

    // ---- Recurrent weights, register-resident as f32x2 pairs. ----
    unsigned long long wh0[16], wh1[16], wh2[16], wh3[16];
    #pragma unroll
    for (int k = 0; k < 16; k++) {
        wh0[k] = ld64(W_hh + (size_t)r0 * HDIM + 2 * lane + 64 * k);
        wh1[k] = ld64(W_hh + (size_t)r1 * HDIM + 2 * lane + 64 * k);
        wh2[k] = ld64(W_hh + (size_t)r2 * HDIM + 2 * lane + 64 * k);
        wh3[k] = ld64(W_hh + (size_t)r3 * HDIM + 2 * lane + 64 * k);
    }

    // ---- Input-projection weights. ----
    unsigned long long wx0[4], wx1[4], wx2[4], wx3[4];
    #pragma unroll
    for (int k = 0; k < 4; k++) {
        wx0[k] = ld64(W_ih + (size_t)r0 * IDIM + 2 * lane + 64 * k);
        wx1[k] = ld64(W_ih + (size_t)r1 * IDIM + 2 * lane + 64 * k);
        wx2[k] = ld64(W_ih + (size_t)r2 * IDIM + 2 * lane + 64 * k);
        wx3[k] = ld64(W_ih + (size_t)r3 * IDIM + 2 * lane + 64 * k);
    }

    // Per-lane bias + nonlinearity constants for this lane's gate:
    //   sigmoid(x) = 1/(1+exp(-x))        -> pre=-1, postA=1, postB=0
    //   tanh(x)    = 2/(1+exp(-2x)) - 1   -> pre=-2, postA=2, postB=-1 (gate 2)
    const int brow = j + gate * HDIM;           // no array indexing -> no spill
    const float bias_lane = b_ih[brow] + b_hh[brow];
    const float pre   = (gate == 2) ? -2.0f : -1.0f;
    const float postA = (gate == 2) ?  2.0f :  1.0f;
    const float postB = (gate == 2) ? -1.0f :  0.0f;

    // x_t pairs, prefetched one step ahead
    unsigned long long xr[4];
    #pragma unroll
    for (int k = 0; k < 4; k++)
        xr[k] = ld64(seq + 2 * lane + 64 * k);

    float c_state = 0.0f;   // uniform across lanes

    #pragma unroll 1
    for (int t = 0; t < T_STEPS; ++t) {
        // ---- x-projection: independent of h_t, overlaps the poll below. ----
        unsigned long long a0 = 0, a1 = 0, a2 = 0, a3 = 0;
        #pragma unroll
        for (int k = 0; k < 4; k++) {
            fma2(a0, wx0[k], xr[k]);
            fma2(a1, wx1[k], xr[k]);
            fma2(a2, wx2[k], xr[k]);
            fma2(a3, wx3[k], xr[k]);
        }

        // ---- Warp-granular sentinel poll (R6 structure: load inside loop,
        // sticky lanes, vote exit). ----
        const float* p = g_hs + (size_t)t * HDIM + 128 * warp + 4 * lane;
        unsigned int v0, v1, v2, v3;
        int ok = 0;
        do {
            if (!ok) {
                asm volatile("ld.global.cg.v4.b32 {%0,%1,%2,%3}, [%4];"
                             : "=r"(v0), "=r"(v1), "=r"(v2), "=r"(v3) : "l"(p));
                ok = (v0 != NAN_BITS) & (v1 != NAN_BITS) &
                     (v2 != NAN_BITS) & (v3 != NAN_BITS);
            }
        } while (!__all_sync(0xffffffffu, ok));

        // Stage this warp's segment.
        reinterpret_cast<uint4*>(h_s)[tid] = make_uint4(v0, v1, v2, v3);
        __syncthreads();

        // ---- Recurrent matvec: register weights vs SMEM h, packed f32x2. ----
        #pragma unroll
        for (int k = 0; k < 16; k++) {
            unsigned long long hv = ld64(h_s + 2 * lane + 64 * k);
            fma2(a0, wh0[k], hv);
            fma2(a1, wh1[k], hv);
            fma2(a2, wh2[k], hv);
            fma2(a3, wh3[k], hv);
        }

        float s0 = pairsum(a0), s1 = pairsum(a1),
              s2 = pairsum(a2), s3 = pairsum(a3);

        // ---- Merged reduction (proven in R8): 2 merge stages fold the 4
        // gate sums into one value per lane (lane&3 == gate), then a 3-stage
        // butterfly over the 8-lane groups. 5 SHFL + 5 ADD total. ----
        {
            bool hi = (lane & 1);
            float keep01 = hi ? s1 : s0, send01 = hi ? s0 : s1;
            float keep23 = hi ? s3 : s2, send23 = hi ? s2 : s3;
            s0 = keep01 + __shfl_xor_sync(0xffffffffu, send01, 1);
            s2 = keep23 + __shfl_xor_sync(0xffffffffu, send23, 1);
        }
        float w;
        {
            bool hi = (lane & 2);
            float keep = hi ? s2 : s0, send = hi ? s0 : s2;
            w = keep + __shfl_xor_sync(0xffffffffu, send, 2);
        }
        w += __shfl_xor_sync(0xffffffffu, w, 4);
        w += __shfl_xor_sync(0xffffffffu, w, 8);
        w += __shfl_xor_sync(0xffffffffu, w, 16);

        // ---- ONE nonlinearity for all gates (per-lane constants). ----
        float act = fmaf(postA,
                         1.0f / (1.0f + __expf(pre * (w + bias_lane))),
                         postB);
        float i_ = __shfl_sync(0xffffffffu, act, 0);
        float f_ = __shfl_sync(0xffffffffu, act, 1);
        float g_ = __shfl_sync(0xffffffffu, act, 2);
        float o_ = __shfl_sync(0xffffffffu, act, 3);

        c_state = f_ * c_state + i_ * g_;
        float tc = fmaf(2.0f, 1.0f / (1.0f + __expf(-2.0f * c_state)), -1.0f);
        float h_ = o_ * tc;
        if (lane == 0) {
            asm volatile("st.global.cg.f32 [%0], %1;"
                         :: "l"(g_hs + (size_t)(t + 1) * HDIM + j), "f"(h_));
        }
        __syncthreads();    // trailing barrier (R6): parks warps at BAR instead
                            // of letting them spin on L2 — this throttle is
                            // what keeps chip-wide poll traffic under the LTS cap.

        // ---- Prefetch x_{t+1}; latency hides behind the next poll. ----
        if (t + 1 < T_STEPS) {
            const float* xrow = seq + (size_t)(t + 1) * IDIM + 2 * lane;
            #pragma unroll
            for (int k = 0; k < 4; k++)
                xr[k] = ld64(xrow + 64 * k);
        }
    }
}

// out[t] = sigmoid(h_{t+1} . W_out + b_out); one warp per timestep.
__global__ void __launch_bounds__(256)
out_kernel(const float* __restrict__ W_out,
           const float* __restrict__ b_out,
           float* __restrict__ out)
{
    const int warp = threadIdx.x >> 5;
    const int lane = threadIdx.x & 31;
    const int t = blockIdx.x * 8 + warp;
    if (t >= T_STEPS) return;

    const float* hrow = g_hs + (size_t)(t + 1) * HDIM;
    float acc = 0.0f;
    #pragma unroll
    for (int k = 0; k < 32; k++) {
        int c = lane + 32 * k;
        acc = fmaf(hrow[c], W_out[c], acc);
    }
    #pragma unroll
    for (int off = 16; off > 0; off >>= 1)
        acc += __shfl_xor_sync(0xffffffffu, acc, off);
    if (lane == 0)
        out[t] = sigmoid_fast(acc + b_out[0]);
}

extern "C" void kernel_launch(void* const* d_in, const int* in_sizes, int n_in,
                              void* d_out, int out_size)
{
    const float* seq   = (const float*)d_in[0];   // [8192, 256]
    const float* W_ih  = (const float*)d_in[1];   // [4096, 256]
    const float* W_hh  = (const float*)d_in[2];   // [4096, 1024]
    const float* b_ih  = (const float*)d_in[3];   // [4096]
    const float* b_hh  = (const float*)d_in[4];   // [4096]
    const float* W_out = (const float*)d_in[5];   // [1, 1024]
    const float* b_out = (const float*)d_in[6];   // [1]
    float* out = (float*)d_out;                   // [8192, 1]

    init_kernel<<<T_STEPS + 1, NTHREADS>>>();
    lstm_kernel<<<NBLOCKS, NTHREADS>>>(seq, W_ih, W_hh, b_ih, b_hh);
    out_kernel<<<T_STEPS / 8, 256>>>(W_out, b_out, out);
}